// round 15
// baseline (speedup 1.0000x reference)
#include <cuda_runtime.h>
#include <cstdint>

// Problem constants (fixed shapes)
#define BB    256      // batch
#define SS    128      // sequence
#define DD    1024     // d_model
#define DQ    256      // style hidden
#define TXT   768      // caption dim
#define KTOT  1024     // DQ + TXT (concat GEMM K)
#define NSPLIT 8
#define KSPL  128      // KTOT / NSPLIT (splits 0,1 -> hidden; 2..7 -> captions)

// Device scratch (no allocation allowed)
__device__ float g_h[BB * DQ];                // relu(style@W1+b1)
__device__ float g_comb[BB * DD];             // bias-init + REDG-accumulated

// ---- packed f32x2 helpers (sm_103a) -------------------------------------
__device__ __forceinline__ unsigned long long pk2(float lo, float hi) {
    unsigned long long r;
    asm("mov.b64 %0, {%1, %2};" : "=l"(r) : "f"(lo), "f"(hi));
    return r;
}
__device__ __forceinline__ void fma2(unsigned long long& d,
                                     unsigned long long a, unsigned long long b) {
    asm("fma.rn.f32x2 %0, %1, %2, %0;" : "+l"(d) : "l"(a), "l"(b));
}
__device__ __forceinline__ void add2(unsigned long long& d, unsigned long long a) {
    asm("add.rn.f32x2 %0, %0, %1;" : "+l"(d) : "l"(a));
}
__device__ __forceinline__ float2 up2(unsigned long long v) {
    float2 f;
    asm("mov.b64 {%0, %1}, %2;" : "=f"(f.x), "=f"(f.y) : "l"(v));
    return f;
}
// cp.async 16B (cg = L2 only, straight to smem)
__device__ __forceinline__ void cpa16(uint32_t saddr, const void* g) {
    asm volatile("cp.async.cg.shared.global [%0], [%1], 16;"
                 :: "r"(saddr), "l"(g));
}
#define CPA_COMMIT() asm volatile("cp.async.commit_group;")
// streaming (evict-first) float4 store for the big output
__device__ __forceinline__ void stg_cs4(float* p, float4 v) {
    asm volatile("st.global.cs.v4.f32 [%0], {%1,%2,%3,%4};"
                 :: "l"(p), "f"(v.x), "f"(v.y), "f"(v.z), "f"(v.w));
}
// no-return global f32 atomic add (REDG)
__device__ __forceinline__ void redg_add(float* p, float v) {
    asm volatile("red.global.add.f32 [%0], %1;" :: "l"(p), "f"(v) : "memory");
}

// ---------------------------------------------------------------------------
// Kernel 1: hidden = relu(style@W1+b1), padding mask, AND g_comb = b2+tb
// (bias init so the GEMM can REDG-accumulate into it).  All float4.
// ---------------------------------------------------------------------------
#define PREP_HID   (BB * DQ / 4)              // 16384
#define PREP_MASK  (BB * SS / 4)              // 8192
#define PREP_CMB   (BB * DD / 4)              // 65536
#define PREP_TOTAL (PREP_HID + PREP_MASK + PREP_CMB)

__global__ void __launch_bounds__(256) prep_kernel(
    const int*   __restrict__ types,
    const float* __restrict__ style,   // [B,5]
    const float* __restrict__ w1,      // [5,256]
    const float* __restrict__ b1,      // [256]
    const float* __restrict__ b2,      // [1024]
    const float* __restrict__ tb,      // [1024]
    float*       __restrict__ out_mask,
    int          write_mask)
{
    int i4 = blockIdx.x * 256 + threadIdx.x;
    if (i4 < PREP_HID) {
        int b  = i4 >> 6;
        int k4 = (i4 & 63) << 2;
        const float* srow = style + b * 5;
        float s0 = srow[0], s1 = srow[1], s2 = srow[2], s3 = srow[3], s4 = srow[4];
        float4 acc = *reinterpret_cast<const float4*>(b1 + k4);
        #define STEP(si, row) { \
            float4 w = *reinterpret_cast<const float4*>(w1 + (row)*DQ + k4); \
            acc.x = fmaf(si, w.x, acc.x); acc.y = fmaf(si, w.y, acc.y); \
            acc.z = fmaf(si, w.z, acc.z); acc.w = fmaf(si, w.w, acc.w); }
        STEP(s0, 0) STEP(s1, 1) STEP(s2, 2) STEP(s3, 3) STEP(s4, 4)
        #undef STEP
        float4 v = make_float4(fmaxf(acc.x, 0.0f), fmaxf(acc.y, 0.0f),
                               fmaxf(acc.z, 0.0f), fmaxf(acc.w, 0.0f));
        *reinterpret_cast<float4*>(&g_h[b * DQ + k4]) = v;
    } else if (i4 < PREP_HID + PREP_MASK) {
        if (write_mask) {
            int m4 = i4 - PREP_HID;
            int4 t = *reinterpret_cast<const int4*>(types + m4 * 4);
            float4 mv = make_float4(t.x == 0 ? 1.0f : 0.0f, t.y == 0 ? 1.0f : 0.0f,
                                    t.z == 0 ? 1.0f : 0.0f, t.w == 0 ? 1.0f : 0.0f);
            *reinterpret_cast<float4*>(out_mask + m4 * 4) = mv;
        }
    } else if (i4 < PREP_TOTAL) {
        int c4 = i4 - (PREP_HID + PREP_MASK);     // 0..65535
        int n  = (c4 & 255) * 4;
        float4 v2 = *reinterpret_cast<const float4*>(b2 + n);
        float4 vt = *reinterpret_cast<const float4*>(tb + n);
        reinterpret_cast<float4*>(g_comb)[c4] =
            make_float4(v2.x + vt.x, v2.y + vt.y, v2.z + vt.z, v2.w + vt.w);
    }
}

// ---------------------------------------------------------------------------
// Kernel 2: split-K SGEMM, FFMA2, cp.async double-buffered.
// Epilogue now REDG-accumulates directly into g_comb (reduce kernel gone).
// BM=64 BN=128 BK=32, 4m x 8n micro-tile, 256 threads.
// Grid (8 n, 4 m, 8 split) = 256 blocks.
// ---------------------------------------------------------------------------
__global__ void __launch_bounds__(256) gemm_kernel(
    const float* __restrict__ cap,  // [256,768]
    const float* __restrict__ w2,   // [256,1024]
    const float* __restrict__ tw)   // [768,1024]
{
    __shared__ float  As[2][64][36];
    __shared__ float4 Bs[2][32][32];

    const int tid = threadIdx.x;
    const int n0  = blockIdx.x * 128;
    const int m0  = blockIdx.y * 64;
    const int sp  = blockIdx.z;
    const int ks  = sp * KSPL;
    const float* W     = (sp < 2) ? (w2 + ks * DD) : (tw + (ks - DQ) * DD);
    const float* Abase = (sp < 2) ? (g_h + ks)     : (cap + (ks - DQ));
    const int    Astr  = (sp < 2) ? DQ : TXT;

    const int tx = tid & 15;
    const int ty = tid >> 4;

    const uint32_t sAs = (uint32_t)__cvta_generic_to_shared(&As[0][0][0]);
    const uint32_t sBs = (uint32_t)__cvta_generic_to_shared(&Bs[0][0][0]);
    const uint32_t asStage = 64 * 36 * 4;
    const uint32_t bsStage = 32 * 32 * 16;

    const int am0 = tid >> 3, akq = (tid & 7) * 4;
    const int am1 = (tid + 256) >> 3;

    auto load_stage = [&](int st, int k0) {
        uint32_t aB = sAs + st * asStage;
        uint32_t bB = sBs + st * bsStage;
        cpa16(aB + (am0 * 36 + akq) * 4, Abase + (m0 + am0) * Astr + k0 + akq);
        cpa16(aB + (am1 * 36 + akq) * 4, Abase + (m0 + am1) * Astr + k0 + akq);
        #pragma unroll
        for (int i = 0; i < 4; i++) {
            int idx = tid + i * 256;
            int r = idx >> 5, c4 = idx & 31;
            cpa16(bB + (r * 32 + c4) * 16, W + (k0 + r) * DD + n0 + c4 * 4);
        }
        CPA_COMMIT();
    };

    load_stage(0, 0);
    load_stage(1, 32);

    unsigned long long acc[4][2][2] = {};

    #pragma unroll
    for (int it = 0; it < 4; it++) {
        if (it < 3) asm volatile("cp.async.wait_group 1;");
        else        asm volatile("cp.async.wait_group 0;");
        __syncthreads();
        const int st = it & 1;

        #pragma unroll
        for (int kq = 0; kq < 32; kq += 4) {
            float4 am[4];
            #pragma unroll
            for (int r = 0; r < 4; r++)
                am[r] = *reinterpret_cast<const float4*>(&As[st][4 * ty + r][kq]);
            #pragma unroll
            for (int j = 0; j < 4; j++) {
                const int k = kq + j;
                ulonglong2 bL = *reinterpret_cast<const ulonglong2*>(&Bs[st][k][tx]);
                ulonglong2 bH = *reinterpret_cast<const ulonglong2*>(&Bs[st][k][16 + tx]);
                float a0f = (j == 0) ? am[0].x : (j == 1) ? am[0].y : (j == 2) ? am[0].z : am[0].w;
                float a1f = (j == 0) ? am[1].x : (j == 1) ? am[1].y : (j == 2) ? am[1].z : am[1].w;
                float a2f = (j == 0) ? am[2].x : (j == 1) ? am[2].y : (j == 2) ? am[2].z : am[2].w;
                float a3f = (j == 0) ? am[3].x : (j == 1) ? am[3].y : (j == 2) ? am[3].z : am[3].w;
                unsigned long long a0 = pk2(a0f, a0f);
                unsigned long long a1 = pk2(a1f, a1f);
                unsigned long long a2 = pk2(a2f, a2f);
                unsigned long long a3 = pk2(a3f, a3f);
                fma2(acc[0][0][0], a0, bL.x); fma2(acc[0][0][1], a0, bL.y);
                fma2(acc[0][1][0], a0, bH.x); fma2(acc[0][1][1], a0, bH.y);
                fma2(acc[1][0][0], a1, bL.x); fma2(acc[1][0][1], a1, bL.y);
                fma2(acc[1][1][0], a1, bH.x); fma2(acc[1][1][1], a1, bH.y);
                fma2(acc[2][0][0], a2, bL.x); fma2(acc[2][0][1], a2, bL.y);
                fma2(acc[2][1][0], a2, bH.x); fma2(acc[2][1][1], a2, bH.y);
                fma2(acc[3][0][0], a3, bL.x); fma2(acc[3][0][1], a3, bL.y);
                fma2(acc[3][1][0], a3, bH.x); fma2(acc[3][1][1], a3, bH.y);
            }
        }
        __syncthreads();
        if (it + 2 < 4) load_stage(st, (it + 2) * 32);
    }

    // Epilogue: REDG-accumulate partials into bias-initialized g_comb.
    #pragma unroll
    for (int r = 0; r < 4; r++) {
        int m = m0 + 4 * ty + r;
        #pragma unroll
        for (int h = 0; h < 2; h++) {
            float2 p0 = up2(acc[r][h][0]);
            float2 p1 = up2(acc[r][h][1]);
            float* p = &g_comb[m * DD + n0 + 64 * h + 4 * tx];
            redg_add(p + 0, p0.x);
            redg_add(p + 1, p0.y);
            redg_add(p + 2, p1.x);
            redg_add(p + 3, p1.y);
        }
    }
}

// ---------------------------------------------------------------------------
// Kernel 3: assembly v6 = R8 structure (best measured) + smem-staged comb.
//   warp = fixed s, loop over 32 b.
//   ft[5] = femb[s]+temb[k] in REGISTERS (select chain beat both table forms).
//   pemb gather: direct coalesced LDG.128, L1-resident slab (dsl slowest dim).
//   comb staged into smem in preamble -> t==1 path is an LDS.128, not a
//   dependent L2 load.
// smem: comb 16KB + ts/ix 4KB.  Grid (bchunk=8, schunk=8, dsl=8) = 512 blocks.
// ---------------------------------------------------------------------------
__global__ void __launch_bounds__(512) emb_kernel(
    const int*   __restrict__ types,
    const int*   __restrict__ inds,
    const float* __restrict__ temb,   // [5,1024]
    const float* __restrict__ pemb,   // [128,1024]
    const float* __restrict__ femb,   // [128,1024]
    float*       __restrict__ out)
{
    __shared__ float4 combS[32 * 32];   // [bb][d4] 16KB
    __shared__ int    tsS[32 * 16];
    __shared__ int    ixS[32 * 16];

    const int tid = threadIdx.x;
    const int d4  = tid & 31;
    const int sg  = tid >> 5;                  // warp id = local s (0..15)
    const int b0  = blockIdx.x * 32;
    const int s0  = blockIdx.y * 16;
    const int dsl = blockIdx.z;                // slowest -> slab locality
    const int d   = dsl * 128 + d4 * 4;
    const int s   = s0 + sg;

    if (tid < 128) {
        int b_ = tid >> 2, q = (tid & 3) * 4;
        *reinterpret_cast<int4*>(&tsS[b_ * 16 + q]) =
            *reinterpret_cast<const int4*>(&types[(b0 + b_) * SS + s0 + q]);
    } else if (tid < 256) {
        int j = tid - 128;
        int b_ = j >> 2, q = (j & 3) * 4;
        *reinterpret_cast<int4*>(&ixS[b_ * 16 + q]) =
            *reinterpret_cast<const int4*>(&inds[(b0 + b_) * SS + s0 + q]);
    }
    // Stage comb[b0..b0+31] for this d-slab: 1024 float4, 2 per thread,
    // coalesced 512B rows.
    #pragma unroll
    for (int i = tid; i < 32 * 32; i += 512) {
        int bb = i >> 5, c = i & 31;
        combS[i] = *reinterpret_cast<const float4*>(
            &g_comb[(b0 + bb) * DD + dsl * 128 + c * 4]);
    }

    // ft[k] = femb[s] + temb[k], k=0..4 — registers, loop-invariant
    const float4 fr = *reinterpret_cast<const float4*>(&femb[s * DD + d]);
    float4 ft[5];
    #pragma unroll
    for (int k = 0; k < 5; k++) {
        float4 te = *reinterpret_cast<const float4*>(&temb[k * DD + d]);
        ft[k] = make_float4(fr.x + te.x, fr.y + te.y, fr.z + te.z, fr.w + te.w);
    }
    __syncthreads();

    float* obase = out + (size_t)s * DD + d;

    #pragma unroll 4
    for (int bb = 0; bb < 32; bb++) {
        const int t  = tsS[bb * 16 + sg];     // warp-uniform
        const int iv = ixS[bb * 16 + sg];     // warp-uniform
        const float4 pe = *reinterpret_cast<const float4*>(&pemb[iv * DD + d]);
        float4 base = (t == 0) ? ft[0] : (t == 1) ? ft[1] :
                      (t == 2) ? ft[2] : (t == 3) ? ft[3] : ft[4];
        float4 v = make_float4(base.x + pe.x, base.y + pe.y,
                               base.z + pe.z, base.w + pe.w);
        if (t == 1) {   // warp-uniform; conflict-free LDS.128 now
            float4 c = combS[bb * 32 + d4];
            v.x += c.x; v.y += c.y; v.z += c.z; v.w += c.w;
        }
        stg_cs4(obase + (size_t)(b0 + bb) * SS * DD, v);
    }
}

// ---------------------------------------------------------------------------
extern "C" void kernel_launch(void* const* d_in, const int* in_sizes, int n_in,
                              void* d_out, int out_size)
{
    const int*   types = (const int*)  d_in[0];
    const int*   inds  = (const int*)  d_in[1];
    const float* style = (const float*)d_in[2];
    const float* cap   = (const float*)d_in[3];
    const float* temb  = (const float*)d_in[4];
    const float* pemb  = (const float*)d_in[5];
    const float* w1    = (const float*)d_in[6];
    const float* b1    = (const float*)d_in[7];
    const float* w2    = (const float*)d_in[8];
    const float* b2    = (const float*)d_in[9];
    const float* tw    = (const float*)d_in[10];
    const float* tb    = (const float*)d_in[11];
    const float* femb  = (const float*)d_in[12];
    float*       out   = (float*)d_out;

    const long long emb_elems = (long long)BB * SS * DD;
    const int write_mask = (out_size >= emb_elems + BB * SS) ? 1 : 0;

    // 1: hidden + mask + comb bias-init
    prep_kernel<<<(PREP_TOTAL + 255) / 256, 256>>>(
        types, style, w1, b1, b2, tb, out + emb_elems, write_mask);

    // 2: split-K FFMA2 SGEMM, REDG epilogue -> g_comb (reduce kernel deleted)
    gemm_kernel<<<dim3(DD / 128, BB / 64, NSPLIT), 256>>>(cap, w2, tw);

    // 3: assembly (R8 structure + smem comb)
    emb_kernel<<<dim3(8, 8, 8), 512>>>(types, inds, temb, pemb, femb, out);
}